// round 2
// baseline (speedup 1.0000x reference)
#include <cuda_runtime.h>
#include <cstdint>
#include <math.h>

// Problem dims
#define BB 64
#define TT 512
#define II 128
#define HH 512
#define OO 64

#define ALPHA_F 0.1f
#define ONE_M_ALPHA_F 0.9f

// Scratch (allocation-free rule: __device__ globals)
__device__ float g_xproj[TT * BB * HH];   // [t][b][h]  (bias b folded in)
__device__ float g_hist [TT * BB * HH];   // [t][b][h]  h_new history

// ---------------------------------------------------------------------------
// Kernel 1: x_proj[t][b][h] = sum_i inputs[b][t][i] * W_in[h][i] + bias[h]
// grid (2048 row-tiles of 16, 4 h-tiles of 128), block 256
// ---------------------------------------------------------------------------
__global__ __launch_bounds__(256, 2)
void k_xproj(const float* __restrict__ inputs,
             const float* __restrict__ W_in,
             const float* __restrict__ bias) {
    extern __shared__ float smem[];
    float4* W4s = (float4*)smem;          // [128][32] f4 (swizzled)  64KB
    float4* X4s = W4s + 128 * 32;         // [16][32]  f4             8KB
    float*  red = (float*)(X4s + 16 * 32);// [2][128][16] floats     16KB

    const int tid  = threadIdx.x;
    const int row0 = blockIdx.x * 16;     // rows in inputs-order (b*512 + t)
    const int h0   = blockIdx.y * 128;

    const float4* Wg = (const float4*)W_in;     // [512][32]
    for (int idx = tid; idx < 128 * 32; idx += 256) {
        int h = idx >> 5, j = idx & 31;
        W4s[h * 32 + (j ^ (h & 7))] = Wg[(h0 + h) * 32 + j];
    }
    const float4* Xg = (const float4*)inputs;   // [B*T][32]
    for (int idx = tid; idx < 16 * 32; idx += 256) {
        int r = idx >> 5, j = idx & 31;
        X4s[r * 32 + j] = Xg[(row0 + r) * 32 + j];
    }
    __syncthreads();

    const int h  = tid & 127;
    const int ks = tid >> 7;              // 0..1, k-split of 64 each
    const int swz = h & 7;
    const float4* Wrow = W4s + h * 32;

    float acc[16];
    #pragma unroll
    for (int i = 0; i < 16; i++) acc[i] = 0.f;

    #pragma unroll 4
    for (int jj = 0; jj < 16; jj++) {
        int j = ks * 16 + jj;
        float4 w = Wrow[j ^ swz];
        #pragma unroll
        for (int i = 0; i < 16; i++) {
            float4 x = X4s[i * 32 + j];
            acc[i] += w.x * x.x + w.y * x.y + w.z * x.z + w.w * x.w;
        }
    }
    float4* R4 = (float4*)red;            // [(ks*128+h)][4] f4 = rows
    #pragma unroll
    for (int q = 0; q < 4; q++)
        R4[(ks * 128 + h) * 4 + q] =
            make_float4(acc[4*q], acc[4*q+1], acc[4*q+2], acc[4*q+3]);
    __syncthreads();

    const int h2 = tid & 127;
    const int rq = tid >> 7;              // 0..1 -> 8 rows each
    float bv = bias[h0 + h2];
    #pragma unroll
    for (int i = 0; i < 8; i++) {
        int r = rq * 8 + i;
        float v = red[(0 * 128 + h2) * 16 + r]
                + red[(1 * 128 + h2) * 16 + r] + bv;
        int rr = row0 + r;
        int b_ = rr >> 9;                 // rr = b*512 + t
        int t_ = rr & 511;
        g_xproj[(t_ * 64 + b_) * 512 + h0 + h2] = v;
    }
}

// ---------------------------------------------------------------------------
// Kernel 2: the scan. 16 clusters x 8 CTAs. Cluster = 4 batch rows.
// CTA rank c owns W_rec rows [c*64, c*64+64) resident in SMEM (128KB).
// h state double-buffered in SMEM, exchanged via DSMEM push + cluster.sync.
// ---------------------------------------------------------------------------
__global__ __launch_bounds__(256, 1)
void k_scan(const float* __restrict__ hidden,
            const float* __restrict__ W_rec) {
    extern __shared__ float smem[];
    float4* W4s = (float4*)smem;          // [64][128] f4 (swizzled) 128KB
    float4* H4s = W4s + 64 * 128;         // [2][4][128] f4           16KB
    float4* Rd4 = H4s + 2 * 4 * 128;      // [4][64] f4 (rows packed)  4KB

    const int tid   = threadIdx.x;
    const int crank = blockIdx.x & 7;     // CTA rank in cluster
    const int b0    = (blockIdx.x >> 3) * 4;
    const int obase = crank * 64;

    // Load W_rec slice (once, stays for all 512 steps)
    const float4* Wg = (const float4*)W_rec;    // [512][128]
    for (int idx = tid; idx < 64 * 128; idx += 256) {
        int oo = idx >> 7, j = idx & 127;
        W4s[oo * 128 + (j ^ (oo & 7))] = Wg[(obase + oo) * 128 + j];
    }
    // Init h buffer 0 with hidden[b0..b0+3][:]
    const float4* hg = (const float4*)hidden;   // [64][128]
    for (int idx = tid; idx < 4 * 128; idx += 256) {
        int r = idx >> 7, j = idx & 127;
        H4s[r * 128 + j] = hg[(b0 + r) * 128 + j];
    }
    __syncthreads();

    const int o   = tid & 63;
    const int ks  = tid >> 6;             // k-split 0..3; == row r in epilogue
    const int swz = o & 7;
    const int cb  = ks * 32;
    const int og  = obase + o;
    const float4* Wrow = W4s + o * 128;
    const float*  redf = (const float*)Rd4;

    uint32_t h_base = (uint32_t)__cvta_generic_to_shared(H4s);

    for (int t = 0; t < TT; t++) {
        const int buf  = t & 1;
        const int nbuf = buf ^ 1;
        // prefetch x_proj for epilogue (r = ks)
        float xp = g_xproj[(t * 64 + b0 + ks) * 512 + og];

        const float4* Hb = H4s + buf * 512;     // [4][128] f4
        float a0 = 0.f, a1 = 0.f, a2 = 0.f, a3 = 0.f;
        #pragma unroll 4
        for (int jj = 0; jj < 32; jj++) {
            int j = cb + jj;
            float4 w  = Wrow[j ^ swz];
            float4 h0v = Hb[      j];
            float4 h1v = Hb[128 + j];
            float4 h2v = Hb[256 + j];
            float4 h3v = Hb[384 + j];
            a0 += w.x*h0v.x + w.y*h0v.y + w.z*h0v.z + w.w*h0v.w;
            a1 += w.x*h1v.x + w.y*h1v.y + w.z*h1v.z + w.w*h1v.w;
            a2 += w.x*h2v.x + w.y*h2v.y + w.z*h2v.z + w.w*h2v.w;
            a3 += w.x*h3v.x + w.y*h3v.y + w.z*h3v.z + w.w*h3v.w;
        }
        Rd4[ks * 64 + o] = make_float4(a0, a1, a2, a3);
        __syncthreads();

        // reduce over the 4 k-splits; this thread finalizes (row ks, col og)
        float pre = xp
                  + redf[(0 * 64 + o) * 4 + ks]
                  + redf[(1 * 64 + o) * 4 + ks]
                  + redf[(2 * 64 + o) * 4 + ks]
                  + redf[(3 * 64 + o) * 4 + ks];
        float hold = ((const float*)Hb)[ks * 512 + og];
        float hnew = ONE_M_ALPHA_F * hold + ALPHA_F * tanhf(pre);

        g_hist[(t * 64 + b0 + ks) * 512 + og] = hnew;

        // push h_new into every cluster CTA's next h buffer (incl. self)
        uint32_t laddr = h_base + (uint32_t)((nbuf * 2048 + ks * 512 + og) * 4);
        #pragma unroll
        for (int rk = 0; rk < 8; rk++) {
            asm volatile(
                "{ .reg .b32 ra;\n"
                "  mapa.shared::cluster.u32 ra, %0, %1;\n"
                "  st.shared::cluster.f32 [ra], %2; }\n"
                :: "r"(laddr), "r"(rk), "f"(hnew) : "memory");
        }
        asm volatile("barrier.cluster.arrive.aligned;" ::: "memory");
        asm volatile("barrier.cluster.wait.aligned;"   ::: "memory");
    }
}

// ---------------------------------------------------------------------------
// Kernel 3: outs[b][t][o] = sum_h g_hist[t][b][h] * W_out[o][h] + b_out[o]
// grid 2048 (16 bt-rows each), block 256
// ---------------------------------------------------------------------------
__global__ __launch_bounds__(256, 1)
void k_out(const float* __restrict__ W_out,
           const float* __restrict__ b_out,
           float* __restrict__ out) {
    extern __shared__ float smem[];
    float4* W4s = (float4*)smem;          // [64][128] f4 (swizzled) 128KB
    float4* R4s = W4s + 64 * 128;         // [16][128] f4             32KB
    float4* Rd4 = R4s + 16 * 128;         // [4][64][4] f4            16KB

    const int tid = threadIdx.x;
    const int bt0 = blockIdx.x * 16;

    const float4* Wg = (const float4*)W_out;    // [64][128]
    for (int idx = tid; idx < 64 * 128; idx += 256) {
        int oo = idx >> 7, j = idx & 127;
        W4s[oo * 128 + (j ^ (oo & 7))] = Wg[oo * 128 + j];
    }
    const float4* Hg = (const float4*)g_hist;
    for (int idx = tid; idx < 16 * 128; idx += 256) {
        int r = idx >> 7, j = idx & 127;
        R4s[r * 128 + j] = Hg[(bt0 + r) * 128 + j];
    }
    __syncthreads();

    const int o   = tid & 63;
    const int ks  = tid >> 6;
    const int swz = o & 7;
    const float4* Wrow = W4s + o * 128;

    float acc[16];
    #pragma unroll
    for (int i = 0; i < 16; i++) acc[i] = 0.f;

    #pragma unroll 2
    for (int jj = 0; jj < 32; jj++) {
        int j = ks * 32 + jj;
        float4 w = Wrow[j ^ swz];
        #pragma unroll
        for (int i = 0; i < 16; i++) {
            float4 h4 = R4s[i * 128 + j];
            acc[i] += w.x*h4.x + w.y*h4.y + w.z*h4.z + w.w*h4.w;
        }
    }
    #pragma unroll
    for (int q = 0; q < 4; q++)
        Rd4[(ks * 64 + o) * 4 + q] =
            make_float4(acc[4*q], acc[4*q+1], acc[4*q+2], acc[4*q+3]);
    __syncthreads();

    const int rq = tid >> 6;              // 4 rows each
    float bo = b_out[o];
    float4 s0 = Rd4[(0 * 64 + o) * 4 + rq];
    float4 s1 = Rd4[(1 * 64 + o) * 4 + rq];
    float4 s2 = Rd4[(2 * 64 + o) * 4 + rq];
    float4 s3 = Rd4[(3 * 64 + o) * 4 + rq];
    float p[4] = { s0.x + s1.x + s2.x + s3.x + bo,
                   s0.y + s1.y + s2.y + s3.y + bo,
                   s0.z + s1.z + s2.z + s3.z + bo,
                   s0.w + s1.w + s2.w + s3.w + bo };
    #pragma unroll
    for (int i = 0; i < 4; i++) {
        int bt = bt0 + rq * 4 + i;
        int t_ = bt >> 6, b_ = bt & 63;
        out[(b_ * 512 + t_) * 64 + o] = p[i];
    }
}

// Copy h_final (= g_hist[T-1]) into the tail of the output buffer.
__global__ void k_hfinal(float* __restrict__ out) {
    int i = blockIdx.x * 256 + threadIdx.x;   // 32768 threads
    out[i] = g_hist[(TT - 1) * BB * HH + i];
}

// ---------------------------------------------------------------------------
extern "C" void kernel_launch(void* const* d_in, const int* in_sizes, int n_in,
                              void* d_out, int out_size) {
    const float* inputs = (const float*)d_in[0];   // [64,512,128]
    const float* hidden = (const float*)d_in[1];   // [64,512]
    const float* W_in   = (const float*)d_in[2];   // [512,128]
    const float* W_rec  = (const float*)d_in[3];   // [512,512]
    const float* bias   = (const float*)d_in[4];   // [512]
    const float* W_out  = (const float*)d_in[5];   // [64,512]
    const float* b_out  = (const float*)d_in[6];   // [64]
    float* out = (float*)d_out;                    // [64,512,64] ++ [64,512]

    const int SMEM1 = (128 * 32 + 16 * 32) * 16 + 2 * 128 * 16 * 4; // 90112
    const int SMEM2 = (64 * 128 + 2 * 4 * 128 + 4 * 64) * 16;       // 151552
    const int SMEM3 = (64 * 128 + 16 * 128 + 4 * 64 * 4) * 16;      // 180224

    cudaFuncSetAttribute(k_xproj, cudaFuncAttributeMaxDynamicSharedMemorySize, SMEM1);
    cudaFuncSetAttribute(k_scan,  cudaFuncAttributeMaxDynamicSharedMemorySize, SMEM2);
    cudaFuncSetAttribute(k_out,   cudaFuncAttributeMaxDynamicSharedMemorySize, SMEM3);

    // 1) input projection (+ bias fold)
    k_xproj<<<dim3(2048, 4), 256, SMEM1>>>(inputs, W_in, bias);

    // 2) sequential scan: 16 clusters x 8 CTAs
    {
        cudaLaunchConfig_t cfg = {};
        cfg.gridDim  = dim3(128, 1, 1);
        cfg.blockDim = dim3(256, 1, 1);
        cfg.dynamicSmemBytes = SMEM2;
        cfg.stream = 0;
        cudaLaunchAttribute attrs[1];
        attrs[0].id = cudaLaunchAttributeClusterDimension;
        attrs[0].val.clusterDim.x = 8;
        attrs[0].val.clusterDim.y = 1;
        attrs[0].val.clusterDim.z = 1;
        cfg.attrs = attrs;
        cfg.numAttrs = 1;
        cudaLaunchKernelEx(&cfg, k_scan, hidden, W_rec);
    }

    // 3) output projection over the whole history
    k_out<<<2048, 256, SMEM3>>>(W_out, b_out, out);

    // 4) h_final
    k_hfinal<<<128, 256>>>(out + BB * TT * OO);
}

// round 3
// speedup vs baseline: 1.1652x; 1.1652x over previous
#include <cuda_runtime.h>
#include <cstdint>
#include <math.h>

// Problem dims
#define BB 64
#define TT 512
#define II 128
#define HH 512
#define OO 64

#define ALPHA_F 0.1f
#define ONE_M_ALPHA_F 0.9f

// Scratch (allocation-free rule: __device__ globals)
__device__ float g_xproj[TT * BB * HH];   // [t][b][h]  (bias folded in)
__device__ float g_hist [TT * BB * HH];   // [t][b][h]  h_new history

// ---------------- packed f32x2 helpers (Blackwell FFMA2) -------------------
__device__ __forceinline__ unsigned long long pk2(float lo, float hi) {
    unsigned long long r;
    asm("mov.b64 %0, {%1, %2};" : "=l"(r) : "f"(lo), "f"(hi));
    return r;
}
__device__ __forceinline__ float2 upk2(unsigned long long v) {
    float2 p;
    asm("mov.b64 {%0, %1}, %2;" : "=f"(p.x), "=f"(p.y) : "l"(v));
    return p;
}
__device__ __forceinline__ unsigned long long ffma2(
    unsigned long long a, unsigned long long b, unsigned long long c) {
    unsigned long long d;
    asm("fma.rn.f32x2 %0, %1, %2, %3;" : "=l"(d) : "l"(a), "l"(b), "l"(c));
    return d;
}

// ---------------------------------------------------------------------------
// Kernel 1: x_proj[t][b][h] = sum_i inputs[b][t][i] * W_in[h][i] + bias[h]
// grid (2048 row-tiles of 16, 4 h-tiles of 128), block 256
// ---------------------------------------------------------------------------
__global__ __launch_bounds__(256, 2)
void k_xproj(const float* __restrict__ inputs,
             const float* __restrict__ W_in,
             const float* __restrict__ bias) {
    extern __shared__ float smem[];
    float4* W4s = (float4*)smem;          // [128][32] f4 (swizzled)  64KB
    float4* X4s = W4s + 128 * 32;         // [16][32]  f4              8KB
    float*  red = (float*)(X4s + 16 * 32);// [2][128][16] floats      16KB

    const int tid  = threadIdx.x;
    const int row0 = blockIdx.x * 16;     // rows in inputs-order (b*512 + t)
    const int h0   = blockIdx.y * 128;

    const float4* Wg = (const float4*)W_in;     // [512][32]
    for (int idx = tid; idx < 128 * 32; idx += 256) {
        int h = idx >> 5, j = idx & 31;
        W4s[h * 32 + (j ^ (h & 7))] = Wg[(h0 + h) * 32 + j];
    }
    const float4* Xg = (const float4*)inputs;   // [B*T][32]
    for (int idx = tid; idx < 16 * 32; idx += 256) {
        int r = idx >> 5, j = idx & 31;
        X4s[r * 32 + j] = Xg[(row0 + r) * 32 + j];
    }
    __syncthreads();

    const int h  = tid & 127;
    const int ks = tid >> 7;              // 0..1, k-split of 64 each
    const int swz = h & 7;
    const float4* Wrow = W4s + h * 32;

    unsigned long long acc2[16];
    #pragma unroll
    for (int i = 0; i < 16; i++) acc2[i] = 0ull;

    #pragma unroll 4
    for (int jj = 0; jj < 16; jj++) {
        int j = ks * 16 + jj;
        float4 w = Wrow[j ^ swz];
        unsigned long long wlo = pk2(w.x, w.y);
        unsigned long long whi = pk2(w.z, w.w);
        #pragma unroll
        for (int i = 0; i < 16; i++) {
            float4 x = X4s[i * 32 + j];
            acc2[i] = ffma2(wlo, pk2(x.x, x.y), acc2[i]);
            acc2[i] = ffma2(whi, pk2(x.z, x.w), acc2[i]);
        }
    }
    float acc[16];
    #pragma unroll
    for (int i = 0; i < 16; i++) { float2 p = upk2(acc2[i]); acc[i] = p.x + p.y; }

    float4* R4 = (float4*)red;            // [(ks*128+h)][4] f4 = rows
    #pragma unroll
    for (int q = 0; q < 4; q++)
        R4[(ks * 128 + h) * 4 + q] =
            make_float4(acc[4*q], acc[4*q+1], acc[4*q+2], acc[4*q+3]);
    __syncthreads();

    const int h2 = tid & 127;
    const int rq = tid >> 7;              // 0..1 -> 8 rows each
    float bv = bias[h0 + h2];
    #pragma unroll
    for (int i = 0; i < 8; i++) {
        int r = rq * 8 + i;
        float v = red[(0 * 128 + h2) * 16 + r]
                + red[(1 * 128 + h2) * 16 + r] + bv;
        int rr = row0 + r;
        int b_ = rr >> 9;                 // rr = b*512 + t
        int t_ = rr & 511;
        g_xproj[(t_ * 64 + b_) * 512 + h0 + h2] = v;
    }
}

// ---------------------------------------------------------------------------
// Kernel 2: the scan. 16 clusters x 8 CTAs. Cluster = 4 batch rows.
// CTA rank c owns W_rec rows [c*64, c*64+64), held in REGISTERS
// (128 regs/thread). h state double-buffered in SMEM; mainloop h loads are
// warp-uniform (broadcast). Exchange via vectorized DSMEM push + cluster.sync.
// ---------------------------------------------------------------------------
__global__ __launch_bounds__(256, 1)
void k_scan(const float* __restrict__ hidden,
            const float* __restrict__ W_rec) {
    extern __shared__ float smem[];
    float* Hbuf = smem;                       // [2][4][512] floats = 16KB
    float4* Rd4 = (float4*)(smem + 4096);     // [4][64] float4      = 4KB

    const int tid   = threadIdx.x;
    const int crank = blockIdx.x & 7;         // CTA rank in cluster
    const int b0    = (blockIdx.x >> 3) * 4;
    const int obase = crank * 64;

    const int o   = tid & 63;
    const int ks  = tid >> 6;                 // k-split 0..3 (128 k each)
    const int og  = obase + o;

    // --- W_rec slice into registers: W_rec[og][ks*128 .. ks*128+127] ---
    unsigned long long wr[64];
    {
        const ulonglong2* Wg2 =
            (const ulonglong2*)(W_rec + og * 512 + ks * 128);
        #pragma unroll
        for (int jj = 0; jj < 32; jj++) {
            ulonglong2 p = Wg2[jj];
            wr[2*jj]     = p.x;
            wr[2*jj + 1] = p.y;
        }
    }

    // Init h buffer 0 with hidden[b0..b0+3][:]
    for (int idx = tid; idx < 4 * 512; idx += 256) {
        int r = idx >> 9, j = idx & 511;
        Hbuf[r * 512 + j] = hidden[(b0 + r) * 512 + j];
    }
    __syncthreads();

    const float* redf = (const float*)Rd4;
    uint32_t h_base = (uint32_t)__cvta_generic_to_shared(Hbuf);

    for (int t = 0; t < TT; t++) {
        const int buf  = t & 1;
        const int nbuf = buf ^ 1;
        // prefetch x_proj for the epilogue (row = ks, col = og)
        float xp = g_xproj[(t * 64 + b0 + ks) * 512 + og];

        const ulonglong2* Hb2 =
            (const ulonglong2*)(Hbuf + buf * 2048) + ks * 32;  // row stride 128 ull2
        unsigned long long a0 = 0ull, a1 = 0ull, a2 = 0ull, a3 = 0ull;
        #pragma unroll
        for (int jj = 0; jj < 32; jj++) {
            ulonglong2 h0 = Hb2[          jj];   // broadcast loads (warp-uniform)
            ulonglong2 h1 = Hb2[128     + jj];
            ulonglong2 h2 = Hb2[2 * 128 + jj];
            ulonglong2 h3 = Hb2[3 * 128 + jj];
            unsigned long long w0 = wr[2*jj], w1 = wr[2*jj + 1];
            a0 = ffma2(w0, h0.x, a0); a0 = ffma2(w1, h0.y, a0);
            a1 = ffma2(w0, h1.x, a1); a1 = ffma2(w1, h1.y, a1);
            a2 = ffma2(w0, h2.x, a2); a2 = ffma2(w1, h2.y, a2);
            a3 = ffma2(w0, h3.x, a3); a3 = ffma2(w1, h3.y, a3);
        }
        float2 p0 = upk2(a0), p1 = upk2(a1), p2 = upk2(a2), p3 = upk2(a3);
        Rd4[ks * 64 + o] = make_float4(p0.x + p0.y, p1.x + p1.y,
                                       p2.x + p2.y, p3.x + p3.y);
        __syncthreads();

        // reduce over the 4 k-splits; this thread finalizes (row ks, col og)
        float pre = xp
                  + redf[(0 * 64 + o) * 4 + ks]
                  + redf[(1 * 64 + o) * 4 + ks]
                  + redf[(2 * 64 + o) * 4 + ks]
                  + redf[(3 * 64 + o) * 4 + ks];
        float hold = Hbuf[buf * 2048 + ks * 512 + og];
        float hnew = ONE_M_ALPHA_F * hold + ALPHA_F * tanhf(pre);

        g_hist[(t * 64 + b0 + ks) * 512 + og] = hnew;
        Hbuf[nbuf * 2048 + ks * 512 + og] = hnew;   // local next-buffer
        __syncthreads();

        // vectorized push of our 4x64 slice to the 7 peer CTAs
        if (tid < 64) {
            int r  = tid >> 4;
            int c4 = tid & 15;
            int off = nbuf * 2048 + r * 512 + obase + c4 * 4;
            float4 v = *(const float4*)(Hbuf + off);
            uint32_t laddr = h_base + (uint32_t)(off * 4);
            #pragma unroll
            for (int rk = 0; rk < 8; rk++) {
                if (rk == crank) continue;
                asm volatile(
                    "{ .reg .b32 ra;\n"
                    "  mapa.shared::cluster.u32 ra, %0, %1;\n"
                    "  st.shared::cluster.v4.f32 [ra], {%2, %3, %4, %5}; }\n"
                    :: "r"(laddr), "r"(rk),
                       "f"(v.x), "f"(v.y), "f"(v.z), "f"(v.w) : "memory");
            }
        }
        asm volatile("barrier.cluster.arrive.aligned;" ::: "memory");
        asm volatile("barrier.cluster.wait.aligned;"   ::: "memory");
    }
}

// ---------------------------------------------------------------------------
// Kernel 3: outs[b][t][o] = sum_h g_hist[t][b][h] * W_out[o][h] + b_out[o]
// grid 2048 (16 bt-rows each), block 256
// ---------------------------------------------------------------------------
__global__ __launch_bounds__(256, 1)
void k_out(const float* __restrict__ W_out,
           const float* __restrict__ b_out,
           float* __restrict__ out) {
    extern __shared__ float smem[];
    float4* W4s = (float4*)smem;          // [64][128] f4 (swizzled) 128KB
    float4* R4s = W4s + 64 * 128;         // [16][128] f4             32KB
    float4* Rd4 = R4s + 16 * 128;         // [4][64][4] f4            16KB

    const int tid = threadIdx.x;
    const int bt0 = blockIdx.x * 16;

    const float4* Wg = (const float4*)W_out;    // [64][128]
    for (int idx = tid; idx < 64 * 128; idx += 256) {
        int oo = idx >> 7, j = idx & 127;
        W4s[oo * 128 + (j ^ (oo & 7))] = Wg[oo * 128 + j];
    }
    const float4* Hg = (const float4*)g_hist;
    for (int idx = tid; idx < 16 * 128; idx += 256) {
        int r = idx >> 7, j = idx & 127;
        R4s[r * 128 + j] = Hg[(bt0 + r) * 128 + j];
    }
    __syncthreads();

    const int o   = tid & 63;
    const int ks  = tid >> 6;
    const int swz = o & 7;
    const float4* Wrow = W4s + o * 128;

    unsigned long long acc2[16];
    #pragma unroll
    for (int i = 0; i < 16; i++) acc2[i] = 0ull;

    #pragma unroll 2
    for (int jj = 0; jj < 32; jj++) {
        int j = ks * 32 + jj;
        float4 w = Wrow[j ^ swz];
        unsigned long long wlo = pk2(w.x, w.y);
        unsigned long long whi = pk2(w.z, w.w);
        #pragma unroll
        for (int i = 0; i < 16; i++) {
            float4 h4 = R4s[i * 128 + j];
            acc2[i] = ffma2(wlo, pk2(h4.x, h4.y), acc2[i]);
            acc2[i] = ffma2(whi, pk2(h4.z, h4.w), acc2[i]);
        }
    }
    float acc[16];
    #pragma unroll
    for (int i = 0; i < 16; i++) { float2 p = upk2(acc2[i]); acc[i] = p.x + p.y; }

    #pragma unroll
    for (int q = 0; q < 4; q++)
        Rd4[(ks * 64 + o) * 4 + q] =
            make_float4(acc[4*q], acc[4*q+1], acc[4*q+2], acc[4*q+3]);
    __syncthreads();

    const int rq = tid >> 6;              // 4 rows each
    float bo = b_out[o];
    float4 s0 = Rd4[(0 * 64 + o) * 4 + rq];
    float4 s1 = Rd4[(1 * 64 + o) * 4 + rq];
    float4 s2 = Rd4[(2 * 64 + o) * 4 + rq];
    float4 s3 = Rd4[(3 * 64 + o) * 4 + rq];
    float p[4] = { s0.x + s1.x + s2.x + s3.x + bo,
                   s0.y + s1.y + s2.y + s3.y + bo,
                   s0.z + s1.z + s2.z + s3.z + bo,
                   s0.w + s1.w + s2.w + s3.w + bo };
    #pragma unroll
    for (int i = 0; i < 4; i++) {
        int bt = bt0 + rq * 4 + i;
        int t_ = bt >> 6, b_ = bt & 63;
        out[(b_ * 512 + t_) * 64 + o] = p[i];
    }
}

// Copy h_final (= g_hist[T-1]) into the tail of the output buffer.
__global__ void k_hfinal(float* __restrict__ out) {
    int i = blockIdx.x * 256 + threadIdx.x;   // 32768 threads
    out[i] = g_hist[(TT - 1) * BB * HH + i];
}

// ---------------------------------------------------------------------------
extern "C" void kernel_launch(void* const* d_in, const int* in_sizes, int n_in,
                              void* d_out, int out_size) {
    const float* inputs = (const float*)d_in[0];   // [64,512,128]
    const float* hidden = (const float*)d_in[1];   // [64,512]
    const float* W_in   = (const float*)d_in[2];   // [512,128]
    const float* W_rec  = (const float*)d_in[3];   // [512,512]
    const float* bias   = (const float*)d_in[4];   // [512]
    const float* W_out  = (const float*)d_in[5];   // [64,512]
    const float* b_out  = (const float*)d_in[6];   // [64]
    float* out = (float*)d_out;                    // [64,512,64] ++ [64,512]

    const int SMEM1 = (128 * 32 + 16 * 32) * 16 + 2 * 128 * 16 * 4; // 90112
    const int SMEM2 = (2 * 4 * 512 + 4 * 64 * 4) * 4;               // 20480
    const int SMEM3 = (64 * 128 + 16 * 128 + 4 * 64 * 4) * 16;      // 180224

    cudaFuncSetAttribute(k_xproj, cudaFuncAttributeMaxDynamicSharedMemorySize, SMEM1);
    cudaFuncSetAttribute(k_scan,  cudaFuncAttributeMaxDynamicSharedMemorySize, SMEM2);
    cudaFuncSetAttribute(k_out,   cudaFuncAttributeMaxDynamicSharedMemorySize, SMEM3);

    // 1) input projection (+ bias fold)
    k_xproj<<<dim3(2048, 4), 256, SMEM1>>>(inputs, W_in, bias);

    // 2) sequential scan: 16 clusters x 8 CTAs
    {
        cudaLaunchConfig_t cfg = {};
        cfg.gridDim  = dim3(128, 1, 1);
        cfg.blockDim = dim3(256, 1, 1);
        cfg.dynamicSmemBytes = SMEM2;
        cfg.stream = 0;
        cudaLaunchAttribute attrs[1];
        attrs[0].id = cudaLaunchAttributeClusterDimension;
        attrs[0].val.clusterDim.x = 8;
        attrs[0].val.clusterDim.y = 1;
        attrs[0].val.clusterDim.z = 1;
        cfg.attrs = attrs;
        cfg.numAttrs = 1;
        cudaLaunchKernelEx(&cfg, k_scan, hidden, W_rec);
    }

    // 3) output projection over the whole history
    k_out<<<2048, 256, SMEM3>>>(W_out, b_out, out);

    // 4) h_final
    k_hfinal<<<128, 256>>>(out + BB * TT * OO);
}

// round 4
// speedup vs baseline: 1.5473x; 1.3280x over previous
#include <cuda_runtime.h>
#include <cstdint>
#include <math.h>

// Problem dims
#define BB 64
#define TT 512
#define II 128
#define HH 512
#define OO 64

#define ALPHA_F 0.1f
#define ONE_M_ALPHA_F 0.9f

// Scratch (allocation-free rule: __device__ globals)
__device__ float g_xproj[TT * BB * HH];   // [t][b][h]  (bias folded in)
__device__ float g_hist [TT * BB * HH];   // [t][b][h]  h_new history

// ---------------- packed f32x2 helpers (Blackwell FFMA2) -------------------
__device__ __forceinline__ unsigned long long pk2(float lo, float hi) {
    unsigned long long r;
    asm("mov.b64 %0, {%1, %2};" : "=l"(r) : "f"(lo), "f"(hi));
    return r;
}
__device__ __forceinline__ float2 upk2(unsigned long long v) {
    float2 p;
    asm("mov.b64 {%0, %1}, %2;" : "=f"(p.x), "=f"(p.y) : "l"(v));
    return p;
}
__device__ __forceinline__ unsigned long long ffma2(
    unsigned long long a, unsigned long long b, unsigned long long c) {
    unsigned long long d;
    asm("fma.rn.f32x2 %0, %1, %2, %3;" : "=l"(d) : "l"(a), "l"(b), "l"(c));
    return d;
}

__device__ __forceinline__ void mbar_wait(uint32_t mbar, uint32_t parity) {
    asm volatile(
        "{\n\t"
        ".reg .pred P1;\n\t"
        "WAIT_LOOP_%=:\n\t"
        "mbarrier.try_wait.parity.acquire.cta.shared::cta.b64 P1, [%0], %1, 0x989680;\n\t"
        "@P1 bra.uni WAIT_DONE_%=;\n\t"
        "bra.uni WAIT_LOOP_%=;\n\t"
        "WAIT_DONE_%=:\n\t"
        "}"
        :: "r"(mbar), "r"(parity) : "memory");
}

// ---------------------------------------------------------------------------
// Kernel 1: x_proj[t][b][h] = sum_i inputs[b][t][i] * W_in[h][i] + bias[h]
// ---------------------------------------------------------------------------
__global__ __launch_bounds__(256, 2)
void k_xproj(const float* __restrict__ inputs,
             const float* __restrict__ W_in,
             const float* __restrict__ bias) {
    extern __shared__ float smem[];
    float4* W4s = (float4*)smem;          // [128][32] f4 (swizzled)  64KB
    float4* X4s = W4s + 128 * 32;         // [16][32]  f4              8KB
    float*  red = (float*)(X4s + 16 * 32);// [2][128][16] floats      16KB

    const int tid  = threadIdx.x;
    const int row0 = blockIdx.x * 16;     // rows in inputs-order (b*512 + t)
    const int h0   = blockIdx.y * 128;

    const float4* Wg = (const float4*)W_in;     // [512][32]
    for (int idx = tid; idx < 128 * 32; idx += 256) {
        int h = idx >> 5, j = idx & 31;
        W4s[h * 32 + (j ^ (h & 7))] = Wg[(h0 + h) * 32 + j];
    }
    const float4* Xg = (const float4*)inputs;   // [B*T][32]
    for (int idx = tid; idx < 16 * 32; idx += 256) {
        int r = idx >> 5, j = idx & 31;
        X4s[r * 32 + j] = Xg[(row0 + r) * 32 + j];
    }
    __syncthreads();

    const int h  = tid & 127;
    const int ks = tid >> 7;              // 0..1, k-split of 64 each
    const int swz = h & 7;
    const float4* Wrow = W4s + h * 32;

    unsigned long long acc2[16];
    #pragma unroll
    for (int i = 0; i < 16; i++) acc2[i] = 0ull;

    #pragma unroll 4
    for (int jj = 0; jj < 16; jj++) {
        int j = ks * 16 + jj;
        float4 w = Wrow[j ^ swz];
        unsigned long long wlo = pk2(w.x, w.y);
        unsigned long long whi = pk2(w.z, w.w);
        #pragma unroll
        for (int i = 0; i < 16; i++) {
            float4 x = X4s[i * 32 + j];
            acc2[i] = ffma2(wlo, pk2(x.x, x.y), acc2[i]);
            acc2[i] = ffma2(whi, pk2(x.z, x.w), acc2[i]);
        }
    }
    float acc[16];
    #pragma unroll
    for (int i = 0; i < 16; i++) { float2 p = upk2(acc2[i]); acc[i] = p.x + p.y; }

    float4* R4 = (float4*)red;            // [(ks*128+h)][4] f4 = rows
    #pragma unroll
    for (int q = 0; q < 4; q++)
        R4[(ks * 128 + h) * 4 + q] =
            make_float4(acc[4*q], acc[4*q+1], acc[4*q+2], acc[4*q+3]);
    __syncthreads();

    const int h2 = tid & 127;
    const int rq = tid >> 7;              // 0..1 -> 8 rows each
    float bv = bias[h0 + h2];
    #pragma unroll
    for (int i = 0; i < 8; i++) {
        int r = rq * 8 + i;
        float v = red[(0 * 128 + h2) * 16 + r]
                + red[(1 * 128 + h2) * 16 + r] + bv;
        int rr = row0 + r;
        int b_ = rr >> 9;                 // rr = b*512 + t
        int t_ = rr & 511;
        g_xproj[(t_ * 64 + b_) * 512 + h0 + h2] = v;
    }
}

// ---------------------------------------------------------------------------
// Kernel 2: the scan. 16 clusters x 8 CTAs. Cluster = 4 batch rows.
// W_rec slice in registers. h double-buffered in SMEM. Inter-CTA exchange via
// st.async + mbarrier complete_tx (NO cluster.sync in the loop).
// ---------------------------------------------------------------------------
__global__ __launch_bounds__(256, 1)
void k_scan(const float* __restrict__ hidden,
            const float* __restrict__ W_rec) {
    extern __shared__ float smem[];
    float*  Hbuf = smem;                      // [2][4][512] floats = 16KB
    float4* Rd4  = (float4*)(smem + 4096);    // [4][64] float4      = 4KB
    // mbarriers: full[0], full[1] at byte offsets 20480, 20488
    uint32_t smem_u32 = (uint32_t)__cvta_generic_to_shared(smem);
    const uint32_t mb_full = smem_u32 + 20480;

    const int tid   = threadIdx.x;
    const int crank = blockIdx.x & 7;         // CTA rank in cluster
    const int b0    = (blockIdx.x >> 3) * 4;
    const int obase = crank * 64;

    const int o   = tid & 63;
    const int ks  = tid >> 6;                 // k-split 0..3 (128 k each)
    const int og  = obase + o;

    // --- W_rec slice into registers: W_rec[og][ks*128 .. ks*128+127] ---
    unsigned long long wr[64];
    {
        const ulonglong2* Wg2 =
            (const ulonglong2*)(W_rec + og * 512 + ks * 128);
        #pragma unroll
        for (int jj = 0; jj < 32; jj++) {
            ulonglong2 p = Wg2[jj];
            wr[2*jj]     = p.x;
            wr[2*jj + 1] = p.y;
        }
    }

    // Init h buffer 0 with hidden[b0..b0+3][:]
    for (int idx = tid; idx < 4 * 512; idx += 256) {
        int r = idx >> 9, j = idx & 511;
        Hbuf[r * 512 + j] = hidden[(b0 + r) * 512 + j];
    }

    // Init mbarriers (count=1: the local arm thread)
    if (tid == 0) {
        asm volatile("mbarrier.init.shared.b64 [%0], 1;" :: "r"(mb_full) : "memory");
        asm volatile("mbarrier.init.shared.b64 [%0], 1;" :: "r"(mb_full + 8) : "memory");
        asm volatile("fence.mbarrier_init.release.cluster;" ::: "memory");
    }
    __syncthreads();
    // One cluster barrier: everyone's mbarriers + Hbuf[0] ready before any push
    asm volatile("barrier.cluster.arrive.aligned;" ::: "memory");
    asm volatile("barrier.cluster.wait.aligned;"   ::: "memory");

    // Precompute peer addresses (mapa once)
    uint32_t peer_hbuf[8], peer_mbar[8];
    #pragma unroll
    for (int rk = 0; rk < 8; rk++) {
        asm("mapa.shared::cluster.u32 %0, %1, %2;"
            : "=r"(peer_hbuf[rk]) : "r"(smem_u32), "r"(rk));
        asm("mapa.shared::cluster.u32 %0, %1, %2;"
            : "=r"(peer_mbar[rk]) : "r"(mb_full), "r"(rk));
    }

    const float* redf = (const float*)Rd4;
    int ph0 = 0, ph1 = 0;

    for (int t = 0; t < TT; t++) {
        const int s  = t & 1;
        const int ns = s ^ 1;

        // Arm next-stage barrier for incoming peer bytes (7 peers x 1024B)
        if (t < TT - 1 && tid == 0) {
            asm volatile("mbarrier.arrive.expect_tx.shared.b64 _, [%0], %1;"
                         :: "r"(mb_full + ns * 8), "r"(7168) : "memory");
        }

        // prefetch x_proj for the epilogue (row = ks, col = og)
        float xp = g_xproj[(t * 64 + b0 + ks) * 512 + og];

        // Wait for h(t) to be complete (peers' slices landed)
        if (t > 0) {
            if (s == 0) { mbar_wait(mb_full, ph0); ph0 ^= 1; }
            else        { mbar_wait(mb_full + 8, ph1); ph1 ^= 1; }
        }

        const ulonglong2* Hb2 =
            (const ulonglong2*)(Hbuf + s * 2048) + ks * 32;  // row stride 128 ull2
        unsigned long long a0 = 0ull, a1 = 0ull, a2 = 0ull, a3 = 0ull;
        #pragma unroll
        for (int jj = 0; jj < 32; jj++) {
            ulonglong2 h0 = Hb2[          jj];   // broadcast loads (warp-uniform)
            ulonglong2 h1 = Hb2[128     + jj];
            ulonglong2 h2 = Hb2[2 * 128 + jj];
            ulonglong2 h3 = Hb2[3 * 128 + jj];
            unsigned long long w0 = wr[2*jj], w1 = wr[2*jj + 1];
            a0 = ffma2(w0, h0.x, a0); a0 = ffma2(w1, h0.y, a0);
            a1 = ffma2(w0, h1.x, a1); a1 = ffma2(w1, h1.y, a1);
            a2 = ffma2(w0, h2.x, a2); a2 = ffma2(w1, h2.y, a2);
            a3 = ffma2(w0, h3.x, a3); a3 = ffma2(w1, h3.y, a3);
        }
        float2 p0 = upk2(a0), p1 = upk2(a1), p2 = upk2(a2), p3 = upk2(a3);
        Rd4[ks * 64 + o] = make_float4(p0.x + p0.y, p1.x + p1.y,
                                       p2.x + p2.y, p3.x + p3.y);
        __syncthreads();

        // reduce over the 4 k-splits; this thread finalizes (row ks, col og)
        float pre = xp
                  + redf[(0 * 64 + o) * 4 + ks]
                  + redf[(1 * 64 + o) * 4 + ks]
                  + redf[(2 * 64 + o) * 4 + ks]
                  + redf[(3 * 64 + o) * 4 + ks];
        float hold = Hbuf[s * 2048 + ks * 512 + og];
        float hnew = ONE_M_ALPHA_F * hold + ALPHA_F * tanhf(pre);

        g_hist[(t * 64 + b0 + ks) * 512 + og] = hnew;
        Hbuf[ns * 2048 + ks * 512 + og] = hnew;   // local next-buffer
        __syncthreads();

        // Push our 4x64 slice to the 7 peers via st.async (+complete_tx 16B each)
        if (t < TT - 1 && tid < 64) {
            int r  = tid >> 4;
            int c4 = tid & 15;
            int off = (ns * 2048 + r * 512 + obase + c4 * 4) * 4;  // byte offset
            uint4 v = *(const uint4*)(Hbuf + (off >> 2));
            uint32_t mboff = (uint32_t)(ns * 8);
            #pragma unroll
            for (int rk = 0; rk < 8; rk++) {
                if (rk == crank) continue;
                asm volatile(
                    "st.async.weak.shared::cluster.mbarrier::complete_tx::bytes"
                    ".v4.b32 [%0], {%1, %2, %3, %4}, [%5];"
                    :: "r"(peer_hbuf[rk] + (uint32_t)off),
                       "r"(v.x), "r"(v.y), "r"(v.z), "r"(v.w),
                       "r"(peer_mbar[rk] + mboff) : "memory");
            }
        }
    }
    // Final cluster barrier: don't exit while peers' st.async may be in flight
    asm volatile("barrier.cluster.arrive.aligned;" ::: "memory");
    asm volatile("barrier.cluster.wait.aligned;"   ::: "memory");
}

// ---------------------------------------------------------------------------
// Kernel 3: outs[b][t][o] = sum_h g_hist[t][b][h] * W_out[o][h] + b_out[o]
// Also copies h_final (g_hist[T-1]) into the output tail (blocks 0..63).
// ---------------------------------------------------------------------------
__global__ __launch_bounds__(256, 1)
void k_out(const float* __restrict__ W_out,
           const float* __restrict__ b_out,
           float* __restrict__ out) {
    extern __shared__ float smem[];
    float4* W4s = (float4*)smem;          // [64][128] f4 (swizzled) 128KB
    float4* R4s = W4s + 64 * 128;         // [16][128] f4             32KB
    float4* Rd4 = R4s + 16 * 128;         // [4][64][4] f4            16KB

    const int tid = threadIdx.x;
    const int bt0 = blockIdx.x * 16;

    const float4* Wg = (const float4*)W_out;    // [64][128]
    for (int idx = tid; idx < 64 * 128; idx += 256) {
        int oo = idx >> 7, j = idx & 127;
        W4s[oo * 128 + (j ^ (oo & 7))] = Wg[oo * 128 + j];
    }
    const float4* Hg = (const float4*)g_hist;
    for (int idx = tid; idx < 16 * 128; idx += 256) {
        int r = idx >> 7, j = idx & 127;
        R4s[r * 128 + j] = Hg[(bt0 + r) * 128 + j];
    }
    __syncthreads();

    const int o   = tid & 63;
    const int ks  = tid >> 6;
    const int swz = o & 7;
    const float4* Wrow = W4s + o * 128;

    unsigned long long acc2[16];
    #pragma unroll
    for (int i = 0; i < 16; i++) acc2[i] = 0ull;

    #pragma unroll 2
    for (int jj = 0; jj < 32; jj++) {
        int j = ks * 32 + jj;
        float4 w = Wrow[j ^ swz];
        unsigned long long wlo = pk2(w.x, w.y);
        unsigned long long whi = pk2(w.z, w.w);
        #pragma unroll
        for (int i = 0; i < 16; i++) {
            float4 h4 = R4s[i * 128 + j];
            acc2[i] = ffma2(wlo, pk2(h4.x, h4.y), acc2[i]);
            acc2[i] = ffma2(whi, pk2(h4.z, h4.w), acc2[i]);
        }
    }
    float acc[16];
    #pragma unroll
    for (int i = 0; i < 16; i++) { float2 p = upk2(acc2[i]); acc[i] = p.x + p.y; }

    #pragma unroll
    for (int q = 0; q < 4; q++)
        Rd4[(ks * 64 + o) * 4 + q] =
            make_float4(acc[4*q], acc[4*q+1], acc[4*q+2], acc[4*q+3]);
    __syncthreads();

    const int rq = tid >> 6;              // 4 rows each
    float bo = b_out[o];
    float4 s0 = Rd4[(0 * 64 + o) * 4 + rq];
    float4 s1 = Rd4[(1 * 64 + o) * 4 + rq];
    float4 s2 = Rd4[(2 * 64 + o) * 4 + rq];
    float4 s3 = Rd4[(3 * 64 + o) * 4 + rq];
    float p[4] = { s0.x + s1.x + s2.x + s3.x + bo,
                   s0.y + s1.y + s2.y + s3.y + bo,
                   s0.z + s1.z + s2.z + s3.z + bo,
                   s0.w + s1.w + s2.w + s3.w + bo };
    #pragma unroll
    for (int i = 0; i < 4; i++) {
        int bt = bt0 + rq * 4 + i;
        int t_ = bt >> 6, b_ = bt & 63;
        out[(b_ * 512 + t_) * 64 + o] = p[i];
    }

    // h_final tail: blocks 0..63 each copy one batch row of g_hist[T-1]
    if (blockIdx.x < 64) {
        const float4* src = (const float4*)(g_hist + (TT - 1) * BB * HH
                                            + blockIdx.x * HH);
        float4* dst = (float4*)(out + BB * TT * OO + blockIdx.x * HH);
        if (tid < 128) dst[tid] = src[tid];
    }
}

// ---------------------------------------------------------------------------
extern "C" void kernel_launch(void* const* d_in, const int* in_sizes, int n_in,
                              void* d_out, int out_size) {
    const float* inputs = (const float*)d_in[0];   // [64,512,128]
    const float* hidden = (const float*)d_in[1];   // [64,512]
    const float* W_in   = (const float*)d_in[2];   // [512,128]
    const float* W_rec  = (const float*)d_in[3];   // [512,512]
    const float* bias   = (const float*)d_in[4];   // [512]
    const float* W_out  = (const float*)d_in[5];   // [64,512]
    const float* b_out  = (const float*)d_in[6];   // [64]
    float* out = (float*)d_out;                    // [64,512,64] ++ [64,512]

    const int SMEM1 = (128 * 32 + 16 * 32) * 16 + 2 * 128 * 16 * 4; // 90112
    const int SMEM2 = 20480 + 64;                                    // Hbuf+Rd4+mbars
    const int SMEM3 = (64 * 128 + 16 * 128 + 4 * 64 * 4) * 16;      // 180224

    cudaFuncSetAttribute(k_xproj, cudaFuncAttributeMaxDynamicSharedMemorySize, SMEM1);
    cudaFuncSetAttribute(k_scan,  cudaFuncAttributeMaxDynamicSharedMemorySize, SMEM2);
    cudaFuncSetAttribute(k_out,   cudaFuncAttributeMaxDynamicSharedMemorySize, SMEM3);

    // 1) input projection (+ bias fold)
    k_xproj<<<dim3(2048, 4), 256, SMEM1>>>(inputs, W_in, bias);

    // 2) sequential scan: 16 clusters x 8 CTAs
    {
        cudaLaunchConfig_t cfg = {};
        cfg.gridDim  = dim3(128, 1, 1);
        cfg.blockDim = dim3(256, 1, 1);
        cfg.dynamicSmemBytes = SMEM2;
        cfg.stream = 0;
        cudaLaunchAttribute attrs[1];
        attrs[0].id = cudaLaunchAttributeClusterDimension;
        attrs[0].val.clusterDim.x = 8;
        attrs[0].val.clusterDim.y = 1;
        attrs[0].val.clusterDim.z = 1;
        cfg.attrs = attrs;
        cfg.numAttrs = 1;
        cudaLaunchKernelEx(&cfg, k_scan, hidden, W_rec);
    }

    // 3) output projection over the whole history (+ h_final tail)
    k_out<<<2048, 256, SMEM3>>>(W_out, b_out, out);
}